// round 15
// baseline (speedup 1.0000x reference)
#include <cuda_runtime.h>
#include <cuda_fp16.h>
#include <math.h>
#include <stdint.h>

#define Bn   4
#define Hn   96
#define Wn   320
#define HWn  30720
#define CINn 64
#define HCn  256
#define NCn  3
#define Kn   100
#define NST_M 9
#define NST_H 18

#define MAP_N      (Bn*HCn*HWn)
#define HEAT_N     (Bn*NCn*HWn)
#define OFF_HEAT   0
#define OFF_DEP    (OFF_HEAT + HEAT_N)
#define OFF_DIM    (OFF_DEP + MAP_N)
#define OFF_ROT    (OFF_DIM + MAP_N)
#define OFF_SCORES (OFF_ROT + MAP_N)
#define OFF_POIS   (OFF_SCORES + Bn*Kn)
#define OFF_REG3D  (OFF_POIS + Bn*Kn*384)
#define REG3D_N    (8*8*64*320)
#define MTOT       (Bn*HWn)

#define WMAPS_N (3*18*8192)
#define WHM_N   (NST_H*8192)

__device__ __align__(16) __half g_Xth [Bn*HWn*64];
__device__ __align__(16) __half g_Xloh[Bn*HWn*64];
__device__ __align__(16) __half g_wB2h[WMAPS_N];
__device__ __align__(16) __half g_wHi2[WHM_N];
__device__ __align__(16) __half g_wLo2[WHM_N];
__device__ float g_nms[HEAT_N];
__device__ float g_alpha[4*HCn];
__device__ float g_beta[4*HCn];
__device__ float g_hmpart[2*MTOT*3];
__device__ int   g_sel[Bn*Kn];
__device__ float g_rs[8];

__device__ __forceinline__ void cpz(uint32_t dst, const void* src, unsigned sz) {
    asm volatile("cp.async.cg.shared.global [%0], [%1], 16, %2;"
        :: "r"(dst), "l"(src), "r"(sz));
}
#define CP_COMMIT() asm volatile("cp.async.commit_group;")
#define CP_WAIT(n)  asm volatile("cp.async.wait_group %0;" :: "n"(n))

__device__ __forceinline__ void ldm4(uint32_t* r, uint32_t addr) {
    asm volatile("ldmatrix.sync.aligned.m8n8.x4.shared.b16 {%0,%1,%2,%3}, [%4];"
        : "=r"(r[0]), "=r"(r[1]), "=r"(r[2]), "=r"(r[3]) : "r"(addr));
}

__device__ __forceinline__ void mma16(float* c, const uint32_t* a, uint32_t b0, uint32_t b1) {
    asm volatile("mma.sync.aligned.m16n8k16.row.col.f32.f16.f16.f32 "
        "{%0,%1,%2,%3}, {%4,%5,%6,%7}, {%8,%9}, {%0,%1,%2,%3};"
        : "+f"(c[0]), "+f"(c[1]), "+f"(c[2]), "+f"(c[3])
        : "r"(a[0]), "r"(a[1]), "r"(a[2]), "r"(a[3]), "r"(b0), "r"(b1));
}

// ---------------- prep ----------------
__global__ void prep_kernel(
    const float* b1_0, const float* g_0, const float* be_0, const float* m_0, const float* v_0,
    const float* b1_1, const float* g_1, const float* be_1, const float* m_1, const float* v_1,
    const float* b1_2, const float* g_2, const float* be_2, const float* m_2, const float* v_2,
    const float* b1_3, const float* g_3, const float* be_3, const float* m_3, const float* v_3,
    const float* r3w)
{
    int t = threadIdx.x;
    const float* B1[4] = {b1_0, b1_1, b1_2, b1_3};
    const float* G [4] = {g_0,  g_1,  g_2,  g_3 };
    const float* BE[4] = {be_0, be_1, be_2, be_3};
    const float* M [4] = {m_0,  m_1,  m_2,  m_3 };
    const float* V [4] = {v_0,  v_1,  v_2,  v_3 };
    int h = t >> 8, c = t & 255;
    float inv = G[h][c] * rsqrtf(V[h][c] + 1e-5f);
    g_alpha[t] = inv;
    g_beta[t]  = (B1[h][c] - M[h][c]) * inv + BE[h][c];
    if (t < 8) {
        float s = 0.f;
        for (int i = 0; i < 64; ++i) s += r3w[t*64 + i];
        g_rs[t] = s;
    }
}

// ---------------- channel-last transform (fp16 hi + lo) ----------------
__global__ void xt_kernel(const float* __restrict__ X)
{
    __shared__ float sh[64][33];
    int pg = blockIdx.x;
    int tid = threadIdx.x;
    int b = (pg*32) / HWn;
    int prem = pg*32 - b*HWn;
    #pragma unroll
    for (int i=0;i<8;++i) {
        int idx = i*256 + tid;
        int c = idx >> 5, pix = idx & 31;
        sh[c][pix] = X[((size_t)b*64 + c)*HWn + prem + pix];
    }
    __syncthreads();
    #pragma unroll
    for (int i=0;i<8;++i) {
        int idx = i*256 + tid;
        int pix = idx >> 6, c = idx & 63;
        float v = sh[c][pix];
        __half hv = __float2half_rn(v);
        float lo = v - __half2float(hv);
        size_t o = ((size_t)pg*32 + pix)*64 + c;
        g_Xth [o] = hv;
        g_Xloh[o] = __float2half_rn(lo);
    }
}

// ---------------- merged weight packing ----------------
__global__ void packW(const float* __restrict__ w0, const float* __restrict__ w1,
                      const float* __restrict__ w2, const float* __restrict__ w3)
{
    int idx = blockIdx.x * 256 + threadIdx.x;
    if (idx < WMAPS_N) {
        int head = idx / (18*8192);
        int rr = idx - head*(18*8192);
        int s  = rr >> 13, q = rr & 8191;
        int nh = q >> 12;  int q2 = q & 4095;
        int kc = q2 >> 11; int q3 = q2 & 2047;
        int kh = q3 >> 10; int q4 = q3 & 1023;
        int n  = q4 >> 3;  int e  = q4 & 7;
        int k  = kc*16 + kh*8 + e;
        int ch = (s & 1)*32 + k;
        int pos = s >> 1;
        int ng = nh*128 + n;
        const float* w = (head==0) ? w1 : (head==1) ? w2 : w3;
        g_wB2h[idx] = __float2half_rn(w[ng*576 + ch*9 + pos]);
    } else if (idx < WMAPS_N + WHM_N) {
        int i2 = idx - WMAPS_N;
        int s  = i2 >> 13, q = i2 & 8191;
        int nh = q >> 12;  int q2 = q & 4095;
        int kc = q2 >> 11; int q3 = q2 & 2047;
        int kh = q3 >> 10; int q4 = q3 & 1023;
        int n  = q4 >> 3;  int e  = q4 & 7;
        int k  = kc*16 + kh*8 + e;
        int ch = (s & 1)*32 + k;
        int pos = s >> 1;
        int ng = nh*128 + n;
        float v = w0[ng*576 + ch*9 + pos];
        __half hv = __float2half_rn(v);
        float lo = v - __half2float(hv);
        g_wHi2[i2] = hv;
        g_wLo2[i2] = __float2half_rn(lo);
    }
}

// ---------------- maps conv: 2 m-tiles per CTA, prefetch-over-epilogue ----------------
// buffers 3x32KB @0 (A 16K + B 16K each); chunk @65536 (buf2, 32x129 floats, dead data);
// sal @98304, sbe @98816
#define T_SMEM 99328

__global__ void __launch_bounds__(256, 2) conv_maps(float* __restrict__ out)
{
    extern __shared__ char sm[];
    float* sal = (float*)(sm + 98304);
    float* sbe = (float*)(sm + 98816);
    float* chunk = (float*)(sm + 65536);
    const uint32_t sb = (uint32_t)__cvta_generic_to_shared(sm);

    const int tid = threadIdx.x;
    const int lane = tid & 31;
    const int w = tid >> 5;
    const int wm = w & 3, wn = w >> 2;
    const int g = lane >> 2, cc = lane & 3;
    const int hidx = blockIdx.y >> 1;
    const int nh   = blockIdx.y & 1;
    const int mtile0 = blockIdx.x * 2;

    if (tid < 128) {
        sal[tid] = g_alpha[(hidx+1)*HCn + nh*128 + tid];
        sbe[tid] = g_beta [(hidx+1)*HCn + nh*128 + tid];
    }

    const int m = tid >> 1;
    const int kch = tid & 1;
    const __half* wsrcB = g_wB2h + (size_t)hidx*18*8192;

    auto issueS = [&](int mt, int s, int buf) {
        int mgq = mt*128 + m;
        int bq = mgq / HWn;
        int remq = mgq - bq*HWn;
        int yq = remq / Wn;
        int xq = remq - yq*Wn;
        int ky = s/3, kx = s - ky*3;
        int gy = yq + ky - 1, gx = xq + kx - 1;
        bool valid = ((unsigned)gy < (unsigned)Hn) && ((unsigned)gx < (unsigned)Wn);
        unsigned sz = valid ? 16u : 0u;
        const __half* srcA = valid
            ? g_Xth + ((size_t)((bq*Hn+gy)*Wn + gx))*64 + kch*32
            : g_Xth;
        uint32_t base = sb + buf*32768;
        uint32_t dA = base + (2*kch)*4096 + (m << 4);
        cpz(dA,               srcA,      sz);
        cpz(dA + 2048,        srcA + 8,  sz);
        cpz(dA + 4096,        srcA + 16, sz);
        cpz(dA + 4096 + 2048, srcA + 24, sz);
        const __half* srcB0 = wsrcB + (size_t)(2*s)  *8192 + nh*4096 + tid*16;
        const __half* srcB1 = wsrcB + (size_t)(2*s+1)*8192 + nh*4096 + tid*16;
        uint32_t dB = base + 16384 + tid*32;
        cpz(dB,             srcB0,     16);
        cpz(dB + 16,        srcB0 + 8, 16);
        cpz(dB + 8192,      srcB1,     16);
        cpz(dB + 8192 + 16, srcB1 + 8, 16);
    };

    const int mtx = lane >> 3;
    const uint32_t aoff = ((mtx>>1)*2048) + ((wm*32 + ((mtx&1)<<3) + (lane&7)) << 4);
    const uint32_t boff = ((mtx&1)*2048)  + ((wn*64 + ((mtx>>1)<<3) + (lane&7)) << 4);

    // initial prologue (only once per CTA)
    issueS(mtile0, 0, 0); CP_COMMIT();
    issueS(mtile0, 1, 1); CP_COMMIT();

    for (int t = 0; t < 2; ++t) {
        const int mt = mtile0 + t;

        float acc[2][8][4];
        #pragma unroll
        for (int i=0;i<2;++i)
            #pragma unroll
            for (int j=0;j<8;++j)
                #pragma unroll
                for (int k=0;k<4;++k) acc[i][j][k]=0.f;

        for (int s = 0; s < NST_M; ++s) {
            const int buf = s % 3;
            if (s+1 < NST_M) { CP_WAIT(1); } else { CP_WAIT(0); }
            __syncthreads();

            const uint32_t aB = sb + buf*32768;
            const uint32_t bB = sb + buf*32768 + 16384;
            #pragma unroll
            for (int kc=0;kc<4;++kc) {
                uint32_t a0[4], a1[4], bf[4][4];
                ldm4(a0, aB + kc*4096 + aoff);
                ldm4(a1, aB + kc*4096 + aoff + 256);
                #pragma unroll
                for (int j=0;j<4;++j) ldm4(bf[j], bB + kc*4096 + boff + j*256);
                #pragma unroll
                for (int j=0;j<4;++j) {
                    mma16(acc[0][2*j],   a0, bf[j][0], bf[j][1]);
                    mma16(acc[0][2*j+1], a0, bf[j][2], bf[j][3]);
                    mma16(acc[1][2*j],   a1, bf[j][0], bf[j][1]);
                    mma16(acc[1][2*j+1], a1, bf[j][2], bf[j][3]);
                }
            }
            if (s+2 < NST_M) { issueS(mt, s+2, (s+2)%3); CP_COMMIT(); }
        }

        // prefetch next tile's first two stages BEFORE the epilogue (hides refill)
        if (t == 0) {
            issueS(mtile0+1, 0, 0); CP_COMMIT();
            issueS(mtile0+1, 1, 1); CP_COMMIT();
        }

        // epilogue: 4 rounds of 32 oc; chunk = 32 x 129 floats at buf2 (dead data)
        const int bT = (mt*128) / HWn;
        const int pT = mt*128 - bT*HWn;
        float* obase = out + OFF_DEP + (size_t)hidx*MAP_N + (size_t)bT*HCn*HWn + pT;

        #pragma unroll
        for (int c2 = 0; c2 < 4; ++c2) {
            __syncthreads();
            if (wn == (c2>>1)) {
                #pragma unroll
                for (int m2=0;m2<2;++m2)
                    #pragma unroll
                    for (int j=0;j<4;++j) {
                        int n2g = (c2&1)*4 + j;
                        #pragma unroll
                        for (int e=0;e<4;++e) {
                            int ocl2 = j*8 + 2*cc + (e&1);
                            int oc   = c2*32 + ocl2;
                            int mrow = wm*32 + m2*16 + g + (e>>1)*8;
                            float v = fmaxf(fmaf(acc[m2][n2g][e], sal[oc], sbe[oc]), 0.f);
                            chunk[ocl2*129 + mrow] = v;
                        }
                    }
            }
            __syncthreads();
            const int row = tid & 31;
            const int seg = tid >> 5;
            const float* sp = chunk + row*129 + seg*16;
            float* dst = obase + (size_t)(nh*128 + c2*32 + row)*HWn + seg*16;
            #pragma unroll
            for (int i=0;i<4;++i) {
                float4 v;
                v.x = sp[4*i]; v.y = sp[4*i+1]; v.z = sp[4*i+2]; v.w = sp[4*i+3];
                ((float4*)dst)[i] = v;
            }
        }
    }
}

// ---------------- hm conv: 3xFP16, fp32 acc (R14 proven) ----------------
#define H_SMEM 102400

__global__ void __launch_bounds__(256, 2) conv_hm(const float* __restrict__ hm_w2)
{
    extern __shared__ char sm[];
    float* sal  = (float*)(sm + 98304);
    float* sbe  = (float*)(sm + 98816);
    float* sw2  = (float*)(sm + 99328);
    float* hmbuf= (float*)(sm + 100864);
    const uint32_t sb = (uint32_t)__cvta_generic_to_shared(sm);

    const int tid = threadIdx.x;
    const int lane = tid & 31;
    const int w = tid >> 5;
    const int wm = w & 3, wn = w >> 2;
    const int g = lane >> 2, cc = lane & 3;
    const int nh = blockIdx.y;
    const int mtile = blockIdx.x;

    if (tid < 128) {
        sal[tid] = g_alpha[nh*128 + tid];
        sbe[tid] = g_beta [nh*128 + tid];
        sw2[tid]       = hm_w2[nh*128 + tid];
        sw2[tid + 128] = hm_w2[256 + nh*128 + tid];
        sw2[tid + 256] = hm_w2[512 + nh*128 + tid];
        hmbuf[tid*3] = 0.f; hmbuf[tid*3+1] = 0.f; hmbuf[tid*3+2] = 0.f;
    }

    const int m = tid >> 1;
    const int kch = tid & 1;
    const int mg = mtile*128 + m;
    const int b = mg / HWn;
    const int rem = mg - b*HWn;
    const int y0 = rem / Wn;
    const int x0 = rem - y0*Wn;

    auto issueS = [&](int s, int buf) {
        int p = s >> 1;
        int ky = p/3, kx = p - ky*3;
        int gy = y0 + ky - 1, gx = x0 + kx - 1;
        bool valid = ((unsigned)gy < (unsigned)Hn) && ((unsigned)gx < (unsigned)Wn);
        unsigned sz = valid ? 16u : 0u;
        size_t po = valid ? ((size_t)((b*Hn+gy)*Wn + gx))*64 + (s&1)*32 + kch*16 : 0;
        const __half* sH = g_Xth  + po;
        const __half* sL = g_Xloh + po;
        uint32_t base = sb + buf*32768;
        uint32_t dA = base + (((kch*2)*128 + m) << 4);
        cpz(dA,               sH,     sz);
        cpz(dA + 2048,        sH + 8, sz);
        cpz(dA + 8192,        sL,     sz);
        cpz(dA + 8192 + 2048, sL + 8, sz);
        const __half* bh = g_wHi2 + (size_t)s*8192 + nh*4096 + tid*16;
        const __half* bl = g_wLo2 + (size_t)s*8192 + nh*4096 + tid*16;
        uint32_t dB = base + 16384 + tid*32;
        cpz(dB,             bh,     16);
        cpz(dB + 16,        bh + 8, 16);
        cpz(dB + 8192,      bl,     16);
        cpz(dB + 8192 + 16, bl + 8, 16);
    };

    const int mtx = lane >> 3;
    const uint32_t aoff = ((mtx>>1)*2048) + ((wm*32 + ((mtx&1)<<3) + (lane&7)) << 4);
    const uint32_t boff = ((mtx&1)*2048)  + ((wn*64 + ((mtx>>1)<<3) + (lane&7)) << 4);

    float acc[2][8][4];
    #pragma unroll
    for (int i=0;i<2;++i)
        #pragma unroll
        for (int j=0;j<8;++j)
            #pragma unroll
            for (int k=0;k<4;++k) acc[i][j][k]=0.f;

    issueS(0,0); CP_COMMIT();
    issueS(1,1); CP_COMMIT();

    for (int s = 0; s < NST_H; ++s) {
        const int buf = s % 3;
        if (s+1 < NST_H) { CP_WAIT(1); } else { CP_WAIT(0); }
        __syncthreads();

        const uint32_t base = sb + buf*32768;
        #pragma unroll
        for (int kc=0;kc<2;++kc) {
            uint32_t ah0[4], ah1[4], al0[4], al1[4], bf[4][4];
            ldm4(ah0, base + kc*4096 + aoff);
            ldm4(ah1, base + kc*4096 + aoff + 256);
            #pragma unroll
            for (int j=0;j<4;++j) ldm4(bf[j], base + 16384 + kc*4096 + boff + j*256);
            #pragma unroll
            for (int j=0;j<4;++j) {
                mma16(acc[0][2*j],   ah0, bf[j][0], bf[j][1]);
                mma16(acc[0][2*j+1], ah0, bf[j][2], bf[j][3]);
                mma16(acc[1][2*j],   ah1, bf[j][0], bf[j][1]);
                mma16(acc[1][2*j+1], ah1, bf[j][2], bf[j][3]);
            }
            ldm4(al0, base + 8192 + kc*4096 + aoff);
            ldm4(al1, base + 8192 + kc*4096 + aoff + 256);
            #pragma unroll
            for (int j=0;j<4;++j) {
                mma16(acc[0][2*j],   al0, bf[j][0], bf[j][1]);
                mma16(acc[0][2*j+1], al0, bf[j][2], bf[j][3]);
                mma16(acc[1][2*j],   al1, bf[j][0], bf[j][1]);
                mma16(acc[1][2*j+1], al1, bf[j][2], bf[j][3]);
            }
            #pragma unroll
            for (int j=0;j<4;++j) ldm4(bf[j], base + 24576 + kc*4096 + boff + j*256);
            #pragma unroll
            for (int j=0;j<4;++j) {
                mma16(acc[0][2*j],   ah0, bf[j][0], bf[j][1]);
                mma16(acc[0][2*j+1], ah0, bf[j][2], bf[j][3]);
                mma16(acc[1][2*j],   ah1, bf[j][0], bf[j][1]);
                mma16(acc[1][2*j+1], ah1, bf[j][2], bf[j][3]);
            }
        }
        if (s+2 < NST_H) { issueS(s+2, (s+2)%3); CP_COMMIT(); }
    }

    float hmacc[4][3];
    #pragma unroll
    for (int i=0;i<4;++i) { hmacc[i][0]=0.f; hmacc[i][1]=0.f; hmacc[i][2]=0.f; }

    #pragma unroll
    for (int m2=0;m2<2;++m2)
        #pragma unroll
        for (int n2=0;n2<8;++n2)
            #pragma unroll
            for (int e=0;e<4;++e) {
                int ocl = wn*64 + n2*8 + 2*cc + (e&1);
                float v = fmaxf(fmaf(acc[m2][n2][e], sal[ocl], sbe[ocl]), 0.f);
                int r = m2*2 + (e>>1);
                hmacc[r][0] = fmaf(sw2[ocl],       v, hmacc[r][0]);
                hmacc[r][1] = fmaf(sw2[128 + ocl], v, hmacc[r][1]);
                hmacc[r][2] = fmaf(sw2[256 + ocl], v, hmacc[r][2]);
            }
    #pragma unroll
    for (int o=1;o<4;o<<=1)
        #pragma unroll
        for (int i=0;i<4;++i)
            #pragma unroll
            for (int j=0;j<3;++j)
                hmacc[i][j] += __shfl_xor_sync(0xffffffffu, hmacc[i][j], o);

    __syncthreads();
    if (cc == 0) {
        #pragma unroll
        for (int m2=0;m2<2;++m2)
            #pragma unroll
            for (int t=0;t<2;++t) {
                int mrow = wm*32 + m2*16 + g + t*8;
                #pragma unroll
                for (int j=0;j<3;++j)
                    atomicAdd(&hmbuf[mrow*3 + j], hmacc[m2*2+t][j]);
            }
    }
    __syncthreads();

    if (tid < 128) {
        int midx = mtile*128 + tid;
        #pragma unroll
        for (int j=0;j<3;++j)
            g_hmpart[((size_t)nh*MTOT + midx)*3 + j] = hmbuf[tid*3 + j];
    }
}

// ---------------- heat finish ----------------
__global__ void heat_finish(const float* __restrict__ hm_b2, float* __restrict__ out)
{
    int idx = blockIdx.x * 256 + threadIdx.x;
    if (idx >= MTOT) return;
    int b = idx / HWn;
    int p = idx - b*HWn;
    #pragma unroll
    for (int j=0;j<3;++j) {
        float h = g_hmpart[(size_t)idx*3 + j] + g_hmpart[((size_t)MTOT + idx)*3 + j] + hm_b2[j];
        out[OFF_HEAT + (b*NCn + j)*HWn + p] = 1.f / (1.f + expf(-h));
    }
}

// ---------------- NMS on stored heat ----------------
__global__ void nms_kernel(const float* __restrict__ heat)
{
    int idx = blockIdx.x * blockDim.x + threadIdx.x;
    if (idx >= HEAT_N) return;
    int bc = idx / HWn;
    int p  = idx - bc * HWn;
    int y = p / Wn, x = p - y * Wn;
    const float* base = heat + bc * HWn;
    float c = base[p];
    float mx = c;
    #pragma unroll
    for (int dy = -1; dy <= 1; ++dy) {
        int yy = y + dy;
        if ((unsigned)yy >= (unsigned)Hn) continue;
        #pragma unroll
        for (int dx = -1; dx <= 1; ++dx) {
            int xx = x + dx;
            if ((unsigned)xx >= (unsigned)Wn) continue;
            float v = base[yy * Wn + xx];
            if (v > mx) mx = v;
        }
    }
    g_nms[idx] = (c == mx) ? c : 0.f;
}

// ---------------- per-batch global top-100 (radix select + bitonic) ----------------
__global__ void __launch_bounds__(1024) select_kernel(float* __restrict__ out)
{
    const int b = blockIdx.x;
    const int tid = threadIdx.x;
    const float* src = g_nms + (size_t)b * NCn * HWn;
    const int N = NCn * HWn;

    __shared__ unsigned hist[4096];
    __shared__ unsigned scan_s[32];
    __shared__ int sB1, sC1, sB2;
    __shared__ unsigned candK[512];
    __shared__ unsigned candI[512];
    __shared__ int ccnt;
    __shared__ unsigned long long skey[512];

    for (int i = tid; i < 4096; i += 1024) hist[i] = 0;
    __syncthreads();
    for (int i = tid; i < N; i += 1024) {
        unsigned u = __float_as_uint(src[i]);
        if (u) atomicAdd(&hist[u >> 19], 1);
    }
    __syncthreads();

    {
        int gb = 4*(1023 - tid);
        unsigned h0=hist[gb+3], h1=hist[gb+2], h2=hist[gb+1], h3=hist[gb];
        unsigned tsum = h0+h1+h2+h3;
        unsigned xv = tsum;
        #pragma unroll
        for (int o=1;o<32;o<<=1){ unsigned yv=__shfl_up_sync(0xffffffffu,xv,o); if ((tid&31)>=o) xv+=yv; }
        if ((tid&31)==31) scan_s[tid>>5] = xv;
        __syncthreads();
        if (tid < 32) {
            unsigned yv = scan_s[tid];
            #pragma unroll
            for (int o=1;o<32;o<<=1){ unsigned zv=__shfl_up_sync(0xffffffffu,yv,o); if (tid>=o) yv+=zv; }
            scan_s[tid] = yv;
        }
        __syncthreads();
        unsigned incl = xv + ((tid>=32) ? scan_s[(tid>>5)-1] : 0u);
        unsigned excl = incl - tsum;
        if (excl < (unsigned)Kn && incl >= (unsigned)Kn) {
            unsigned c = excl;
            if (c + h0 >= (unsigned)Kn)            { sB1 = gb+3; sC1 = (int)c; }
            else if (c + h0 + h1 >= (unsigned)Kn)  { sB1 = gb+2; sC1 = (int)(c+h0); }
            else if (c + h0 + h1 + h2 >= (unsigned)Kn) { sB1 = gb+1; sC1 = (int)(c+h0+h1); }
            else                                    { sB1 = gb;   sC1 = (int)(c+h0+h1+h2); }
        }
    }
    __syncthreads();
    const int B1 = sB1;
    const int need = Kn - sC1;

    for (int i = tid; i < 4096; i += 1024) hist[i] = 0;
    __syncthreads();
    for (int i = tid; i < N; i += 1024) {
        unsigned u = __float_as_uint(src[i]);
        if ((int)(u >> 19) == B1) atomicAdd(&hist[(u >> 7) & 0xFFF], 1);
    }
    __syncthreads();
    {
        int gb = 4*(1023 - tid);
        unsigned h0=hist[gb+3], h1=hist[gb+2], h2=hist[gb+1], h3=hist[gb];
        unsigned tsum = h0+h1+h2+h3;
        unsigned xv = tsum;
        #pragma unroll
        for (int o=1;o<32;o<<=1){ unsigned yv=__shfl_up_sync(0xffffffffu,xv,o); if ((tid&31)>=o) xv+=yv; }
        if ((tid&31)==31) scan_s[tid>>5] = xv;
        __syncthreads();
        if (tid < 32) {
            unsigned yv = scan_s[tid];
            #pragma unroll
            for (int o=1;o<32;o<<=1){ unsigned zv=__shfl_up_sync(0xffffffffu,yv,o); if (tid>=o) yv+=zv; }
            scan_s[tid] = yv;
        }
        __syncthreads();
        unsigned incl = xv + ((tid>=32) ? scan_s[(tid>>5)-1] : 0u);
        unsigned excl = incl - tsum;
        if (excl < (unsigned)need && incl >= (unsigned)need) {
            unsigned c = excl;
            if (c + h0 >= (unsigned)need)            sB2 = gb+3;
            else if (c + h0 + h1 >= (unsigned)need)  sB2 = gb+2;
            else if (c + h0 + h1 + h2 >= (unsigned)need) sB2 = gb+1;
            else                                      sB2 = gb;
        }
        if (tid == 0) ccnt = 0;
    }
    __syncthreads();

    const unsigned thr = ((unsigned)B1 << 12) | (unsigned)sB2;
    for (int i = tid; i < N; i += 1024) {
        unsigned u = __float_as_uint(src[i]);
        if ((u >> 7) >= thr) {
            int pos = atomicAdd(&ccnt, 1);
            if (pos < 512) { candK[pos] = u; candI[pos] = (unsigned)i; }
        }
    }
    __syncthreads();

    int n = ccnt; if (n > 512) n = 512;
    for (int i = tid; i < 512; i += 1024)
        skey[i] = (i < n)
            ? ((unsigned long long)candK[i] << 32) | (unsigned)(0xFFFFFFFFu - candI[i])
            : 0ull;
    __syncthreads();
    for (int k = 2; k <= 512; k <<= 1) {
        for (int j = k >> 1; j > 0; j >>= 1) {
            for (int i = tid; i < 512; i += 1024) {
                int ix = i ^ j;
                if (ix > i) {
                    unsigned long long a = skey[i], c = skey[ix];
                    bool desc = ((i & k) == 0);
                    bool sw = desc ? (a < c) : (a > c);
                    if (sw) { skey[i] = c; skey[ix] = a; }
                }
            }
            __syncthreads();
        }
    }

    if (tid < Kn) {
        unsigned long long e = skey[tid];
        unsigned key = (unsigned)(e >> 32);
        unsigned fi  = 0xFFFFFFFFu - (unsigned)(e & 0xFFFFFFFFu);
        out[OFF_SCORES + b*Kn + tid] = __uint_as_float(key);
        g_sel[b*Kn + tid] = (int)(fi % HWn);
    }
}

// ---------------- gather ----------------
__global__ void __launch_bounds__(384) gather_kernel(
    const float* __restrict__ up8, const float* __restrict__ up16, float* __restrict__ out)
{
    int bk = blockIdx.x;
    int b  = bk / Kn;
    int c  = threadIdx.x;
    int ind = g_sel[bk];
    if (ind < 0) ind = 0;
    if (ind > HWn - 1) ind = HWn - 1;
    float val;
    if (c < 128)
        val = up8 [((long long)b*128 + c)       * HWn + (ind >> 1)];
    else
        val = up16[((long long)b*256 + (c-128)) * HWn + (ind >> 2)];
    out[OFF_POIS + bk*384 + c] = val;
}

// ---------------- reg3d ----------------
__global__ void reg3d_kernel(const float* __restrict__ r3b, float* __restrict__ out)
{
    int idx = blockIdx.x * blockDim.x + threadIdx.x;
    if (idx >= REG3D_N) return;
    int o = (idx / (64*320)) & 7;
    out[OFF_REG3D + idx] = g_rs[o] + r3b[o];
}

// ---------------- launch ----------------
extern "C" void kernel_launch(void* const* d_in, const int* in_sizes, int n_in,
                              void* d_out, int out_size)
{
    const float* up16 = (const float*)d_in[0];
    const float* up8  = (const float*)d_in[1];
    const float* up4  = (const float*)d_in[2];

    const float* hm_w1  = (const float*)d_in[3];
    const float* dep_w1 = (const float*)d_in[9];
    const float* dim_w1 = (const float*)d_in[15];
    const float* rot_w1 = (const float*)d_in[21];
    const float* hm_w2  = (const float*)d_in[27];
    const float* hm_b2  = (const float*)d_in[28];
    const float* r3w    = (const float*)d_in[29];
    const float* r3b    = (const float*)d_in[30];

    float* out = (float*)d_out;

    cudaFuncSetAttribute(conv_maps, cudaFuncAttributeMaxDynamicSharedMemorySize, T_SMEM);
    cudaFuncSetAttribute(conv_hm,   cudaFuncAttributeMaxDynamicSharedMemorySize, H_SMEM);

    prep_kernel<<<1, 1024>>>(
        (const float*)d_in[4],  (const float*)d_in[5],  (const float*)d_in[6],  (const float*)d_in[7],  (const float*)d_in[8],
        (const float*)d_in[10], (const float*)d_in[11], (const float*)d_in[12], (const float*)d_in[13], (const float*)d_in[14],
        (const float*)d_in[16], (const float*)d_in[17], (const float*)d_in[18], (const float*)d_in[19], (const float*)d_in[20],
        (const float*)d_in[22], (const float*)d_in[23], (const float*)d_in[24], (const float*)d_in[25], (const float*)d_in[26],
        r3w);
    xt_kernel<<<MTOT/32, 256>>>(up4);
    packW<<<(WMAPS_N + WHM_N + 255)/256, 256>>>(hm_w1, dep_w1, dim_w1, rot_w1);

    conv_maps<<<dim3(480, 6), 256, T_SMEM>>>(out);
    conv_hm<<<dim3(960, 2), 256, H_SMEM>>>(hm_w2);

    heat_finish<<<(MTOT + 255)/256, 256>>>(hm_b2, out);
    nms_kernel<<<(HEAT_N + 255)/256, 256>>>(out + OFF_HEAT);
    select_kernel<<<Bn, 1024>>>(out);
    gather_kernel<<<Bn*Kn, 384>>>(up8, up16, out);
    reg3d_kernel<<<(REG3D_N + 511)/512, 512>>>(r3b, out);
}

// round 16
// speedup vs baseline: 1.0414x; 1.0414x over previous
#include <cuda_runtime.h>
#include <cuda_fp16.h>
#include <math.h>
#include <stdint.h>

#define Bn   4
#define Hn   96
#define Wn   320
#define HWn  30720
#define CINn 64
#define HCn  256
#define NCn  3
#define Kn   100
#define NST_M 9
#define NST_H 18

#define MAP_N      (Bn*HCn*HWn)
#define HEAT_N     (Bn*NCn*HWn)
#define OFF_HEAT   0
#define OFF_DEP    (OFF_HEAT + HEAT_N)
#define OFF_DIM    (OFF_DEP + MAP_N)
#define OFF_ROT    (OFF_DIM + MAP_N)
#define OFF_SCORES (OFF_ROT + MAP_N)
#define OFF_POIS   (OFF_SCORES + Bn*Kn)
#define OFF_REG3D  (OFF_POIS + Bn*Kn*384)
#define REG3D_N    (8*8*64*320)
#define MTOT       (Bn*HWn)

#define WMAPS_N (3*18*8192)
#define WHM_N   (NST_H*8192)

__device__ __align__(16) __half g_Xth [Bn*HWn*64];
__device__ __align__(16) __half g_Xloh[Bn*HWn*64];
__device__ __align__(16) __half g_wB2h[WMAPS_N];
__device__ __align__(16) __half g_wHi2[WHM_N];
__device__ __align__(16) __half g_wLo2[WHM_N];
__device__ float g_nms[HEAT_N];
__device__ float g_alpha[4*HCn];
__device__ float g_beta[4*HCn];
__device__ float g_hmpart[2*MTOT*3];
__device__ int   g_sel[Bn*Kn];
__device__ float g_rs[8];

__device__ __forceinline__ void cpz(uint32_t dst, const void* src, unsigned sz) {
    asm volatile("cp.async.cg.shared.global [%0], [%1], 16, %2;"
        :: "r"(dst), "l"(src), "r"(sz));
}
#define CP_COMMIT() asm volatile("cp.async.commit_group;")
#define CP_WAIT(n)  asm volatile("cp.async.wait_group %0;" :: "n"(n))

__device__ __forceinline__ void ldm4(uint32_t* r, uint32_t addr) {
    asm volatile("ldmatrix.sync.aligned.m8n8.x4.shared.b16 {%0,%1,%2,%3}, [%4];"
        : "=r"(r[0]), "=r"(r[1]), "=r"(r[2]), "=r"(r[3]) : "r"(addr));
}

__device__ __forceinline__ void mma16(float* c, const uint32_t* a, uint32_t b0, uint32_t b1) {
    asm volatile("mma.sync.aligned.m16n8k16.row.col.f32.f16.f16.f32 "
        "{%0,%1,%2,%3}, {%4,%5,%6,%7}, {%8,%9}, {%0,%1,%2,%3};"
        : "+f"(c[0]), "+f"(c[1]), "+f"(c[2]), "+f"(c[3])
        : "r"(a[0]), "r"(a[1]), "r"(a[2]), "r"(a[3]), "r"(b0), "r"(b1));
}

// ---------------- prep ----------------
__global__ void prep_kernel(
    const float* b1_0, const float* g_0, const float* be_0, const float* m_0, const float* v_0,
    const float* b1_1, const float* g_1, const float* be_1, const float* m_1, const float* v_1,
    const float* b1_2, const float* g_2, const float* be_2, const float* m_2, const float* v_2,
    const float* b1_3, const float* g_3, const float* be_3, const float* m_3, const float* v_3,
    const float* r3w)
{
    int t = threadIdx.x;
    const float* B1[4] = {b1_0, b1_1, b1_2, b1_3};
    const float* G [4] = {g_0,  g_1,  g_2,  g_3 };
    const float* BE[4] = {be_0, be_1, be_2, be_3};
    const float* M [4] = {m_0,  m_1,  m_2,  m_3 };
    const float* V [4] = {v_0,  v_1,  v_2,  v_3 };
    int h = t >> 8, c = t & 255;
    float inv = G[h][c] * rsqrtf(V[h][c] + 1e-5f);
    g_alpha[t] = inv;
    g_beta[t]  = (B1[h][c] - M[h][c]) * inv + BE[h][c];
    if (t < 8) {
        float s = 0.f;
        for (int i = 0; i < 64; ++i) s += r3w[t*64 + i];
        g_rs[t] = s;
    }
}

// ---------------- channel-last transform (fp16 hi + lo) ----------------
__global__ void xt_kernel(const float* __restrict__ X)
{
    __shared__ float sh[64][33];
    int pg = blockIdx.x;
    int tid = threadIdx.x;
    int b = (pg*32) / HWn;
    int prem = pg*32 - b*HWn;
    #pragma unroll
    for (int i=0;i<8;++i) {
        int idx = i*256 + tid;
        int c = idx >> 5, pix = idx & 31;
        sh[c][pix] = X[((size_t)b*64 + c)*HWn + prem + pix];
    }
    __syncthreads();
    #pragma unroll
    for (int i=0;i<8;++i) {
        int idx = i*256 + tid;
        int pix = idx >> 6, c = idx & 63;
        float v = sh[c][pix];
        __half hv = __float2half_rn(v);
        float lo = v - __half2float(hv);
        size_t o = ((size_t)pg*32 + pix)*64 + c;
        g_Xth [o] = hv;
        g_Xloh[o] = __float2half_rn(lo);
    }
}

// ---------------- merged weight packing ----------------
__global__ void packW(const float* __restrict__ w0, const float* __restrict__ w1,
                      const float* __restrict__ w2, const float* __restrict__ w3)
{
    int idx = blockIdx.x * 256 + threadIdx.x;
    if (idx < WMAPS_N) {
        int head = idx / (18*8192);
        int rr = idx - head*(18*8192);
        int s  = rr >> 13, q = rr & 8191;
        int nh = q >> 12;  int q2 = q & 4095;
        int kc = q2 >> 11; int q3 = q2 & 2047;
        int kh = q3 >> 10; int q4 = q3 & 1023;
        int n  = q4 >> 3;  int e  = q4 & 7;
        int k  = kc*16 + kh*8 + e;
        int ch = (s & 1)*32 + k;
        int pos = s >> 1;
        int ng = nh*128 + n;
        const float* w = (head==0) ? w1 : (head==1) ? w2 : w3;
        g_wB2h[idx] = __float2half_rn(w[ng*576 + ch*9 + pos]);
    } else if (idx < WMAPS_N + WHM_N) {
        int i2 = idx - WMAPS_N;
        int s  = i2 >> 13, q = i2 & 8191;
        int nh = q >> 12;  int q2 = q & 4095;
        int kc = q2 >> 11; int q3 = q2 & 2047;
        int kh = q3 >> 10; int q4 = q3 & 1023;
        int n  = q4 >> 3;  int e  = q4 & 7;
        int k  = kc*16 + kh*8 + e;
        int ch = (s & 1)*32 + k;
        int pos = s >> 1;
        int ng = nh*128 + n;
        float v = w0[ng*576 + ch*9 + pos];
        __half hv = __float2half_rn(v);
        float lo = v - __half2float(hv);
        g_wHi2[i2] = hv;
        g_wLo2[i2] = __float2half_rn(lo);
    }
}

// ---------------- maps conv: k=64 stages, 3x32KB buffers, 64 mma per window ----------------
// buffer: A 16KB @0, B 16KB @16384; bufs at buf*32768; sal @98304, sbe @98816
#define T_SMEM 99328

__global__ void __launch_bounds__(256, 2) conv_maps(float* __restrict__ out)
{
    extern __shared__ char sm[];
    float* sal = (float*)(sm + 98304);
    float* sbe = (float*)(sm + 98816);
    const uint32_t sb = (uint32_t)__cvta_generic_to_shared(sm);

    const int tid = threadIdx.x;
    const int lane = tid & 31;
    const int w = tid >> 5;
    const int wm = w & 3, wn = w >> 2;
    const int g = lane >> 2, cc = lane & 3;
    const int hidx = blockIdx.y >> 1;
    const int nh   = blockIdx.y & 1;
    const int mtile = blockIdx.x;

    if (tid < 128) {
        sal[tid] = g_alpha[(hidx+1)*HCn + nh*128 + tid];
        sbe[tid] = g_beta [(hidx+1)*HCn + nh*128 + tid];
    }

    const int m = tid >> 1;
    const int kch = tid & 1;
    const int mg = mtile*128 + m;
    const int b = mg / HWn;
    const int rem = mg - b*HWn;
    const int y0 = rem / Wn;
    const int x0 = rem - y0*Wn;

    const __half* wsrcB = g_wB2h + (size_t)hidx*18*8192;

    // stage s = kernel position (64 channels)
    auto issueS = [&](int s, int buf) {
        int ky = s/3, kx = s - ky*3;
        int gy = y0 + ky - 1, gx = x0 + kx - 1;
        bool valid = ((unsigned)gy < (unsigned)Hn) && ((unsigned)gx < (unsigned)Wn);
        unsigned sz = valid ? 16u : 0u;
        const __half* srcA = valid
            ? g_Xth + ((size_t)((b*Hn+gy)*Wn + gx))*64 + kch*32
            : g_Xth;
        uint32_t base = sb + buf*32768;
        uint32_t dA = base + (2*kch)*4096 + (m << 4);
        cpz(dA,               srcA,      sz);
        cpz(dA + 2048,        srcA + 8,  sz);
        cpz(dA + 4096,        srcA + 16, sz);
        cpz(dA + 4096 + 2048, srcA + 24, sz);
        const __half* srcB0 = wsrcB + (size_t)(2*s)  *8192 + nh*4096 + tid*16;
        const __half* srcB1 = wsrcB + (size_t)(2*s+1)*8192 + nh*4096 + tid*16;
        uint32_t dB = base + 16384 + tid*32;
        cpz(dB,           srcB0,     16);
        cpz(dB + 16,      srcB0 + 8, 16);
        cpz(dB + 8192,      srcB1,     16);
        cpz(dB + 8192 + 16, srcB1 + 8, 16);
    };

    const int mtx = lane >> 3;
    const uint32_t aoff = ((mtx>>1)*2048) + ((wm*32 + ((mtx&1)<<3) + (lane&7)) << 4);
    const uint32_t boff = ((mtx&1)*2048)  + ((wn*64 + ((mtx>>1)<<3) + (lane&7)) << 4);

    float acc[2][8][4];
    #pragma unroll
    for (int i=0;i<2;++i)
        #pragma unroll
        for (int j=0;j<8;++j)
            #pragma unroll
            for (int k=0;k<4;++k) acc[i][j][k]=0.f;

    issueS(0,0); CP_COMMIT();
    issueS(1,1); CP_COMMIT();

    for (int s = 0; s < NST_M; ++s) {
        const int buf = s % 3;
        if (s+1 < NST_M) { CP_WAIT(1); } else { CP_WAIT(0); }
        __syncthreads();

        const uint32_t aB = sb + buf*32768;
        const uint32_t bB = sb + buf*32768 + 16384;
        #pragma unroll
        for (int kc=0;kc<4;++kc) {
            uint32_t a0[4], a1[4], bf[4][4];
            ldm4(a0, aB + kc*4096 + aoff);
            ldm4(a1, aB + kc*4096 + aoff + 256);
            #pragma unroll
            for (int j=0;j<4;++j) ldm4(bf[j], bB + kc*4096 + boff + j*256);
            #pragma unroll
            for (int j=0;j<4;++j) {
                mma16(acc[0][2*j],   a0, bf[j][0], bf[j][1]);
                mma16(acc[0][2*j+1], a0, bf[j][2], bf[j][3]);
                mma16(acc[1][2*j],   a1, bf[j][0], bf[j][1]);
                mma16(acc[1][2*j+1], a1, bf[j][2], bf[j][3]);
            }
        }
        if (s+2 < NST_M) { issueS(s+2, (s+2)%3); CP_COMMIT(); }
    }

    const int bT = (mtile*128) / HWn;
    const int pT = mtile*128 - bT*HWn;
    float* obase = out + OFF_DEP + (size_t)hidx*MAP_N + (size_t)bT*HCn*HWn + pT;
    float* chunk = (float*)sm;

    for (int c = 0; c < 2; ++c) {
        __syncthreads();
        if (wn == c) {
            #pragma unroll
            for (int m2=0;m2<2;++m2)
                #pragma unroll
                for (int n2=0;n2<8;++n2)
                    #pragma unroll
                    for (int e=0;e<4;++e) {
                        int mrow = wm*32 + m2*16 + g + (e>>1)*8;
                        int ocl  = n2*8 + 2*cc + (e&1);
                        int oc   = c*64 + ocl;
                        float v = fmaxf(fmaf(acc[m2][n2][e], sal[oc], sbe[oc]), 0.f);
                        chunk[ocl*132 + mrow] = v;
                    }
        }
        __syncthreads();
        const float* sp = chunk + (tid>>2)*132 + (tid&3)*32;
        float* dst = obase + (size_t)(nh*128 + c*64 + (tid>>2))*HWn + (tid&3)*32;
        #pragma unroll
        for (int i=0;i<8;++i)
            ((float4*)dst)[i] = ((const float4*)sp)[i];
    }
}

// ---------------- hm conv: 3xFP16, fp32 acc (proven) ----------------
#define H_SMEM 102400

__global__ void __launch_bounds__(256, 2) conv_hm(const float* __restrict__ hm_w2)
{
    extern __shared__ char sm[];
    float* sal  = (float*)(sm + 98304);
    float* sbe  = (float*)(sm + 98816);
    float* sw2  = (float*)(sm + 99328);
    float* hmbuf= (float*)(sm + 100864);
    const uint32_t sb = (uint32_t)__cvta_generic_to_shared(sm);

    const int tid = threadIdx.x;
    const int lane = tid & 31;
    const int w = tid >> 5;
    const int wm = w & 3, wn = w >> 2;
    const int g = lane >> 2, cc = lane & 3;
    const int nh = blockIdx.y;
    const int mtile = blockIdx.x;

    if (tid < 128) {
        sal[tid] = g_alpha[nh*128 + tid];
        sbe[tid] = g_beta [nh*128 + tid];
        sw2[tid]       = hm_w2[nh*128 + tid];
        sw2[tid + 128] = hm_w2[256 + nh*128 + tid];
        sw2[tid + 256] = hm_w2[512 + nh*128 + tid];
        hmbuf[tid*3] = 0.f; hmbuf[tid*3+1] = 0.f; hmbuf[tid*3+2] = 0.f;
    }

    const int m = tid >> 1;
    const int kch = tid & 1;
    const int mg = mtile*128 + m;
    const int b = mg / HWn;
    const int rem = mg - b*HWn;
    const int y0 = rem / Wn;
    const int x0 = rem - y0*Wn;

    auto issueS = [&](int s, int buf) {
        int p = s >> 1;
        int ky = p/3, kx = p - ky*3;
        int gy = y0 + ky - 1, gx = x0 + kx - 1;
        bool valid = ((unsigned)gy < (unsigned)Hn) && ((unsigned)gx < (unsigned)Wn);
        unsigned sz = valid ? 16u : 0u;
        size_t po = valid ? ((size_t)((b*Hn+gy)*Wn + gx))*64 + (s&1)*32 + kch*16 : 0;
        const __half* sH = g_Xth  + po;
        const __half* sL = g_Xloh + po;
        uint32_t base = sb + buf*32768;
        uint32_t dA = base + (((kch*2)*128 + m) << 4);
        cpz(dA,               sH,     sz);
        cpz(dA + 2048,        sH + 8, sz);
        cpz(dA + 8192,        sL,     sz);
        cpz(dA + 8192 + 2048, sL + 8, sz);
        const __half* bh = g_wHi2 + (size_t)s*8192 + nh*4096 + tid*16;
        const __half* bl = g_wLo2 + (size_t)s*8192 + nh*4096 + tid*16;
        uint32_t dB = base + 16384 + tid*32;
        cpz(dB,             bh,     16);
        cpz(dB + 16,        bh + 8, 16);
        cpz(dB + 8192,      bl,     16);
        cpz(dB + 8192 + 16, bl + 8, 16);
    };

    const int mtx = lane >> 3;
    const uint32_t aoff = ((mtx>>1)*2048) + ((wm*32 + ((mtx&1)<<3) + (lane&7)) << 4);
    const uint32_t boff = ((mtx&1)*2048)  + ((wn*64 + ((mtx>>1)<<3) + (lane&7)) << 4);

    float acc[2][8][4];
    #pragma unroll
    for (int i=0;i<2;++i)
        #pragma unroll
        for (int j=0;j<8;++j)
            #pragma unroll
            for (int k=0;k<4;++k) acc[i][j][k]=0.f;

    issueS(0,0); CP_COMMIT();
    issueS(1,1); CP_COMMIT();

    for (int s = 0; s < NST_H; ++s) {
        const int buf = s % 3;
        if (s+1 < NST_H) { CP_WAIT(1); } else { CP_WAIT(0); }
        __syncthreads();

        const uint32_t base = sb + buf*32768;
        #pragma unroll
        for (int kc=0;kc<2;++kc) {
            uint32_t ah0[4], ah1[4], al0[4], al1[4], bf[4][4];
            ldm4(ah0, base + kc*4096 + aoff);
            ldm4(ah1, base + kc*4096 + aoff + 256);
            #pragma unroll
            for (int j=0;j<4;++j) ldm4(bf[j], base + 16384 + kc*4096 + boff + j*256);
            #pragma unroll
            for (int j=0;j<4;++j) {
                mma16(acc[0][2*j],   ah0, bf[j][0], bf[j][1]);
                mma16(acc[0][2*j+1], ah0, bf[j][2], bf[j][3]);
                mma16(acc[1][2*j],   ah1, bf[j][0], bf[j][1]);
                mma16(acc[1][2*j+1], ah1, bf[j][2], bf[j][3]);
            }
            ldm4(al0, base + 8192 + kc*4096 + aoff);
            ldm4(al1, base + 8192 + kc*4096 + aoff + 256);
            #pragma unroll
            for (int j=0;j<4;++j) {
                mma16(acc[0][2*j],   al0, bf[j][0], bf[j][1]);
                mma16(acc[0][2*j+1], al0, bf[j][2], bf[j][3]);
                mma16(acc[1][2*j],   al1, bf[j][0], bf[j][1]);
                mma16(acc[1][2*j+1], al1, bf[j][2], bf[j][3]);
            }
            #pragma unroll
            for (int j=0;j<4;++j) ldm4(bf[j], base + 24576 + kc*4096 + boff + j*256);
            #pragma unroll
            for (int j=0;j<4;++j) {
                mma16(acc[0][2*j],   ah0, bf[j][0], bf[j][1]);
                mma16(acc[0][2*j+1], ah0, bf[j][2], bf[j][3]);
                mma16(acc[1][2*j],   ah1, bf[j][0], bf[j][1]);
                mma16(acc[1][2*j+1], ah1, bf[j][2], bf[j][3]);
            }
        }
        if (s+2 < NST_H) { issueS(s+2, (s+2)%3); CP_COMMIT(); }
    }

    float hmacc[4][3];
    #pragma unroll
    for (int i=0;i<4;++i) { hmacc[i][0]=0.f; hmacc[i][1]=0.f; hmacc[i][2]=0.f; }

    #pragma unroll
    for (int m2=0;m2<2;++m2)
        #pragma unroll
        for (int n2=0;n2<8;++n2)
            #pragma unroll
            for (int e=0;e<4;++e) {
                int ocl = wn*64 + n2*8 + 2*cc + (e&1);
                float v = fmaxf(fmaf(acc[m2][n2][e], sal[ocl], sbe[ocl]), 0.f);
                int r = m2*2 + (e>>1);
                hmacc[r][0] = fmaf(sw2[ocl],       v, hmacc[r][0]);
                hmacc[r][1] = fmaf(sw2[128 + ocl], v, hmacc[r][1]);
                hmacc[r][2] = fmaf(sw2[256 + ocl], v, hmacc[r][2]);
            }
    #pragma unroll
    for (int o=1;o<4;o<<=1)
        #pragma unroll
        for (int i=0;i<4;++i)
            #pragma unroll
            for (int j=0;j<3;++j)
                hmacc[i][j] += __shfl_xor_sync(0xffffffffu, hmacc[i][j], o);

    __syncthreads();
    if (cc == 0) {
        #pragma unroll
        for (int m2=0;m2<2;++m2)
            #pragma unroll
            for (int t=0;t<2;++t) {
                int mrow = wm*32 + m2*16 + g + t*8;
                #pragma unroll
                for (int j=0;j<3;++j)
                    atomicAdd(&hmbuf[mrow*3 + j], hmacc[m2*2+t][j]);
            }
    }
    __syncthreads();

    if (tid < 128) {
        int midx = mtile*128 + tid;
        #pragma unroll
        for (int j=0;j<3;++j)
            g_hmpart[((size_t)nh*MTOT + midx)*3 + j] = hmbuf[tid*3 + j];
    }
}

// ---------------- heat finish ----------------
__global__ void heat_finish(const float* __restrict__ hm_b2, float* __restrict__ out)
{
    int idx = blockIdx.x * 256 + threadIdx.x;
    if (idx >= MTOT) return;
    int b = idx / HWn;
    int p = idx - b*HWn;
    #pragma unroll
    for (int j=0;j<3;++j) {
        float h = g_hmpart[(size_t)idx*3 + j] + g_hmpart[((size_t)MTOT + idx)*3 + j] + hm_b2[j];
        out[OFF_HEAT + (b*NCn + j)*HWn + p] = 1.f / (1.f + expf(-h));
    }
}

// ---------------- NMS on stored heat ----------------
__global__ void nms_kernel(const float* __restrict__ heat)
{
    int idx = blockIdx.x * blockDim.x + threadIdx.x;
    if (idx >= HEAT_N) return;
    int bc = idx / HWn;
    int p  = idx - bc * HWn;
    int y = p / Wn, x = p - y * Wn;
    const float* base = heat + bc * HWn;
    float c = base[p];
    float mx = c;
    #pragma unroll
    for (int dy = -1; dy <= 1; ++dy) {
        int yy = y + dy;
        if ((unsigned)yy >= (unsigned)Hn) continue;
        #pragma unroll
        for (int dx = -1; dx <= 1; ++dx) {
            int xx = x + dx;
            if ((unsigned)xx >= (unsigned)Wn) continue;
            float v = base[yy * Wn + xx];
            if (v > mx) mx = v;
        }
    }
    g_nms[idx] = (c == mx) ? c : 0.f;
}

// ---------------- per-batch global top-100 (radix select + bitonic) ----------------
__global__ void __launch_bounds__(1024) select_kernel(float* __restrict__ out)
{
    const int b = blockIdx.x;
    const int tid = threadIdx.x;
    const float* src = g_nms + (size_t)b * NCn * HWn;
    const int N = NCn * HWn;

    __shared__ unsigned hist[4096];
    __shared__ unsigned scan_s[32];
    __shared__ int sB1, sC1, sB2;
    __shared__ unsigned candK[512];
    __shared__ unsigned candI[512];
    __shared__ int ccnt;
    __shared__ unsigned long long skey[512];

    for (int i = tid; i < 4096; i += 1024) hist[i] = 0;
    __syncthreads();
    for (int i = tid; i < N; i += 1024) {
        unsigned u = __float_as_uint(src[i]);
        if (u) atomicAdd(&hist[u >> 19], 1);
    }
    __syncthreads();

    {
        int gb = 4*(1023 - tid);
        unsigned h0=hist[gb+3], h1=hist[gb+2], h2=hist[gb+1], h3=hist[gb];
        unsigned tsum = h0+h1+h2+h3;
        unsigned xv = tsum;
        #pragma unroll
        for (int o=1;o<32;o<<=1){ unsigned yv=__shfl_up_sync(0xffffffffu,xv,o); if ((tid&31)>=o) xv+=yv; }
        if ((tid&31)==31) scan_s[tid>>5] = xv;
        __syncthreads();
        if (tid < 32) {
            unsigned yv = scan_s[tid];
            #pragma unroll
            for (int o=1;o<32;o<<=1){ unsigned zv=__shfl_up_sync(0xffffffffu,yv,o); if (tid>=o) yv+=zv; }
            scan_s[tid] = yv;
        }
        __syncthreads();
        unsigned incl = xv + ((tid>=32) ? scan_s[(tid>>5)-1] : 0u);
        unsigned excl = incl - tsum;
        if (excl < (unsigned)Kn && incl >= (unsigned)Kn) {
            unsigned c = excl;
            if (c + h0 >= (unsigned)Kn)            { sB1 = gb+3; sC1 = (int)c; }
            else if (c + h0 + h1 >= (unsigned)Kn)  { sB1 = gb+2; sC1 = (int)(c+h0); }
            else if (c + h0 + h1 + h2 >= (unsigned)Kn) { sB1 = gb+1; sC1 = (int)(c+h0+h1); }
            else                                    { sB1 = gb;   sC1 = (int)(c+h0+h1+h2); }
        }
    }
    __syncthreads();
    const int B1 = sB1;
    const int need = Kn - sC1;

    for (int i = tid; i < 4096; i += 1024) hist[i] = 0;
    __syncthreads();
    for (int i = tid; i < N; i += 1024) {
        unsigned u = __float_as_uint(src[i]);
        if ((int)(u >> 19) == B1) atomicAdd(&hist[(u >> 7) & 0xFFF], 1);
    }
    __syncthreads();
    {
        int gb = 4*(1023 - tid);
        unsigned h0=hist[gb+3], h1=hist[gb+2], h2=hist[gb+1], h3=hist[gb];
        unsigned tsum = h0+h1+h2+h3;
        unsigned xv = tsum;
        #pragma unroll
        for (int o=1;o<32;o<<=1){ unsigned yv=__shfl_up_sync(0xffffffffu,xv,o); if ((tid&31)>=o) xv+=yv; }
        if ((tid&31)==31) scan_s[tid>>5] = xv;
        __syncthreads();
        if (tid < 32) {
            unsigned yv = scan_s[tid];
            #pragma unroll
            for (int o=1;o<32;o<<=1){ unsigned zv=__shfl_up_sync(0xffffffffu,yv,o); if (tid>=o) yv+=zv; }
            scan_s[tid] = yv;
        }
        __syncthreads();
        unsigned incl = xv + ((tid>=32) ? scan_s[(tid>>5)-1] : 0u);
        unsigned excl = incl - tsum;
        if (excl < (unsigned)need && incl >= (unsigned)need) {
            unsigned c = excl;
            if (c + h0 >= (unsigned)need)            sB2 = gb+3;
            else if (c + h0 + h1 >= (unsigned)need)  sB2 = gb+2;
            else if (c + h0 + h1 + h2 >= (unsigned)need) sB2 = gb+1;
            else                                      sB2 = gb;
        }
        if (tid == 0) ccnt = 0;
    }
    __syncthreads();

    const unsigned thr = ((unsigned)B1 << 12) | (unsigned)sB2;
    for (int i = tid; i < N; i += 1024) {
        unsigned u = __float_as_uint(src[i]);
        if ((u >> 7) >= thr) {
            int pos = atomicAdd(&ccnt, 1);
            if (pos < 512) { candK[pos] = u; candI[pos] = (unsigned)i; }
        }
    }
    __syncthreads();

    int n = ccnt; if (n > 512) n = 512;
    for (int i = tid; i < 512; i += 1024)
        skey[i] = (i < n)
            ? ((unsigned long long)candK[i] << 32) | (unsigned)(0xFFFFFFFFu - candI[i])
            : 0ull;
    __syncthreads();
    for (int k = 2; k <= 512; k <<= 1) {
        for (int j = k >> 1; j > 0; j >>= 1) {
            for (int i = tid; i < 512; i += 1024) {
                int ix = i ^ j;
                if (ix > i) {
                    unsigned long long a = skey[i], c = skey[ix];
                    bool desc = ((i & k) == 0);
                    bool sw = desc ? (a < c) : (a > c);
                    if (sw) { skey[i] = c; skey[ix] = a; }
                }
            }
            __syncthreads();
        }
    }

    if (tid < Kn) {
        unsigned long long e = skey[tid];
        unsigned key = (unsigned)(e >> 32);
        unsigned fi  = 0xFFFFFFFFu - (unsigned)(e & 0xFFFFFFFFu);
        out[OFF_SCORES + b*Kn + tid] = __uint_as_float(key);
        g_sel[b*Kn + tid] = (int)(fi % HWn);
    }
}

// ---------------- gather ----------------
__global__ void __launch_bounds__(384) gather_kernel(
    const float* __restrict__ up8, const float* __restrict__ up16, float* __restrict__ out)
{
    int bk = blockIdx.x;
    int b  = bk / Kn;
    int c  = threadIdx.x;
    int ind = g_sel[bk];
    if (ind < 0) ind = 0;
    if (ind > HWn - 1) ind = HWn - 1;
    float val;
    if (c < 128)
        val = up8 [((long long)b*128 + c)       * HWn + (ind >> 1)];
    else
        val = up16[((long long)b*256 + (c-128)) * HWn + (ind >> 2)];
    out[OFF_POIS + bk*384 + c] = val;
}

// ---------------- reg3d ----------------
__global__ void reg3d_kernel(const float* __restrict__ r3b, float* __restrict__ out)
{
    int idx = blockIdx.x * blockDim.x + threadIdx.x;
    if (idx >= REG3D_N) return;
    int o = (idx / (64*320)) & 7;
    out[OFF_REG3D + idx] = g_rs[o] + r3b[o];
}

// ---------------- launch ----------------
extern "C" void kernel_launch(void* const* d_in, const int* in_sizes, int n_in,
                              void* d_out, int out_size)
{
    const float* up16 = (const float*)d_in[0];
    const float* up8  = (const float*)d_in[1];
    const float* up4  = (const float*)d_in[2];

    const float* hm_w1  = (const float*)d_in[3];
    const float* dep_w1 = (const float*)d_in[9];
    const float* dim_w1 = (const float*)d_in[15];
    const float* rot_w1 = (const float*)d_in[21];
    const float* hm_w2  = (const float*)d_in[27];
    const float* hm_b2  = (const float*)d_in[28];
    const float* r3w    = (const float*)d_in[29];
    const float* r3b    = (const float*)d_in[30];

    float* out = (float*)d_out;

    cudaFuncSetAttribute(conv_maps, cudaFuncAttributeMaxDynamicSharedMemorySize, T_SMEM);
    cudaFuncSetAttribute(conv_hm,   cudaFuncAttributeMaxDynamicSharedMemorySize, H_SMEM);

    prep_kernel<<<1, 1024>>>(
        (const float*)d_in[4],  (const float*)d_in[5],  (const float*)d_in[6],  (const float*)d_in[7],  (const float*)d_in[8],
        (const float*)d_in[10], (const float*)d_in[11], (const float*)d_in[12], (const float*)d_in[13], (const float*)d_in[14],
        (const float*)d_in[16], (const float*)d_in[17], (const float*)d_in[18], (const float*)d_in[19], (const float*)d_in[20],
        (const float*)d_in[22], (const float*)d_in[23], (const float*)d_in[24], (const float*)d_in[25], (const float*)d_in[26],
        r3w);
    xt_kernel<<<MTOT/32, 256>>>(up4);
    packW<<<(WMAPS_N + WHM_N + 255)/256, 256>>>(hm_w1, dep_w1, dim_w1, rot_w1);

    conv_maps<<<dim3(960, 6), 256, T_SMEM>>>(out);
    conv_hm<<<dim3(960, 2), 256, H_SMEM>>>(hm_w2);

    heat_finish<<<(MTOT + 255)/256, 256>>>(hm_b2, out);
    nms_kernel<<<(HEAT_N + 255)/256, 256>>>(out + OFF_HEAT);
    select_kernel<<<Bn, 1024>>>(out);
    gather_kernel<<<Bn*Kn, 384>>>(up8, up16, out);
    reg3d_kernel<<<(REG3D_N + 511)/512, 512>>>(r3b, out);
}

// round 17
// speedup vs baseline: 1.0585x; 1.0164x over previous
#include <cuda_runtime.h>
#include <cuda_fp16.h>
#include <math.h>
#include <stdint.h>

#define Bn   4
#define Hn   96
#define Wn   320
#define HWn  30720
#define CINn 64
#define HCn  256
#define NCn  3
#define Kn   100
#define NST_M 9
#define NST_H 18

#define MAP_N      (Bn*HCn*HWn)
#define HEAT_N     (Bn*NCn*HWn)
#define OFF_HEAT   0
#define OFF_DEP    (OFF_HEAT + HEAT_N)
#define OFF_DIM    (OFF_DEP + MAP_N)
#define OFF_ROT    (OFF_DIM + MAP_N)
#define OFF_SCORES (OFF_ROT + MAP_N)
#define OFF_POIS   (OFF_SCORES + Bn*Kn)
#define OFF_REG3D  (OFF_POIS + Bn*Kn*384)
#define REG3D_N    (8*8*64*320)
#define MTOT       (Bn*HWn)

#define WMAPS_N (3*18*8192)
#define WHM_N   (NST_H*8192)

__device__ __align__(16) __half g_Xth [Bn*HWn*64];
__device__ __align__(16) __half g_Xloh[Bn*HWn*64];
__device__ __align__(16) __half g_wB2h[WMAPS_N];
__device__ __align__(16) __half g_wHi2[WHM_N];
__device__ __align__(16) __half g_wLo2[WHM_N];
__device__ float g_nms[HEAT_N];
__device__ float g_alpha[4*HCn];
__device__ float g_beta[4*HCn];
__device__ float g_hmpart[2*MTOT*3];
__device__ int   g_sel[Bn*Kn];
__device__ float g_rs[8];

__device__ __forceinline__ void cpz(uint32_t dst, const void* src, unsigned sz) {
    asm volatile("cp.async.cg.shared.global [%0], [%1], 16, %2;"
        :: "r"(dst), "l"(src), "r"(sz));
}
#define CP_COMMIT() asm volatile("cp.async.commit_group;")
#define CP_WAIT(n)  asm volatile("cp.async.wait_group %0;" :: "n"(n))

__device__ __forceinline__ void ldm4(uint32_t* r, uint32_t addr) {
    asm volatile("ldmatrix.sync.aligned.m8n8.x4.shared.b16 {%0,%1,%2,%3}, [%4];"
        : "=r"(r[0]), "=r"(r[1]), "=r"(r[2]), "=r"(r[3]) : "r"(addr));
}

__device__ __forceinline__ void mma16(float* c, const uint32_t* a, uint32_t b0, uint32_t b1) {
    asm volatile("mma.sync.aligned.m16n8k16.row.col.f32.f16.f16.f32 "
        "{%0,%1,%2,%3}, {%4,%5,%6,%7}, {%8,%9}, {%0,%1,%2,%3};"
        : "+f"(c[0]), "+f"(c[1]), "+f"(c[2]), "+f"(c[3])
        : "r"(a[0]), "r"(a[1]), "r"(a[2]), "r"(a[3]), "r"(b0), "r"(b1));
}

// ---------------- prep ----------------
__global__ void prep_kernel(
    const float* b1_0, const float* g_0, const float* be_0, const float* m_0, const float* v_0,
    const float* b1_1, const float* g_1, const float* be_1, const float* m_1, const float* v_1,
    const float* b1_2, const float* g_2, const float* be_2, const float* m_2, const float* v_2,
    const float* b1_3, const float* g_3, const float* be_3, const float* m_3, const float* v_3,
    const float* r3w)
{
    int t = threadIdx.x;
    const float* B1[4] = {b1_0, b1_1, b1_2, b1_3};
    const float* G [4] = {g_0,  g_1,  g_2,  g_3 };
    const float* BE[4] = {be_0, be_1, be_2, be_3};
    const float* M [4] = {m_0,  m_1,  m_2,  m_3 };
    const float* V [4] = {v_0,  v_1,  v_2,  v_3 };
    int h = t >> 8, c = t & 255;
    float inv = G[h][c] * rsqrtf(V[h][c] + 1e-5f);
    g_alpha[t] = inv;
    g_beta[t]  = (B1[h][c] - M[h][c]) * inv + BE[h][c];
    if (t < 8) {
        float s = 0.f;
        for (int i = 0; i < 64; ++i) s += r3w[t*64 + i];
        g_rs[t] = s;
    }
}

// ---------------- channel-last transform (fp16 hi + lo) ----------------
__global__ void xt_kernel(const float* __restrict__ X)
{
    __shared__ float sh[64][33];
    int pg = blockIdx.x;
    int tid = threadIdx.x;
    int b = (pg*32) / HWn;
    int prem = pg*32 - b*HWn;
    #pragma unroll
    for (int i=0;i<8;++i) {
        int idx = i*256 + tid;
        int c = idx >> 5, pix = idx & 31;
        sh[c][pix] = X[((size_t)b*64 + c)*HWn + prem + pix];
    }
    __syncthreads();
    #pragma unroll
    for (int i=0;i<8;++i) {
        int idx = i*256 + tid;
        int pix = idx >> 6, c = idx & 63;
        float v = sh[c][pix];
        __half hv = __float2half_rn(v);
        float lo = v - __half2float(hv);
        size_t o = ((size_t)pg*32 + pix)*64 + c;
        g_Xth [o] = hv;
        g_Xloh[o] = __float2half_rn(lo);
    }
}

// ---------------- merged weight packing ----------------
__global__ void packW(const float* __restrict__ w0, const float* __restrict__ w1,
                      const float* __restrict__ w2, const float* __restrict__ w3)
{
    int idx = blockIdx.x * 256 + threadIdx.x;
    if (idx < WMAPS_N) {
        int head = idx / (18*8192);
        int rr = idx - head*(18*8192);
        int s  = rr >> 13, q = rr & 8191;
        int nh = q >> 12;  int q2 = q & 4095;
        int kc = q2 >> 11; int q3 = q2 & 2047;
        int kh = q3 >> 10; int q4 = q3 & 1023;
        int n  = q4 >> 3;  int e  = q4 & 7;
        int k  = kc*16 + kh*8 + e;
        int ch = (s & 1)*32 + k;
        int pos = s >> 1;
        int ng = nh*128 + n;
        const float* w = (head==0) ? w1 : (head==1) ? w2 : w3;
        g_wB2h[idx] = __float2half_rn(w[ng*576 + ch*9 + pos]);
    } else if (idx < WMAPS_N + WHM_N) {
        int i2 = idx - WMAPS_N;
        int s  = i2 >> 13, q = i2 & 8191;
        int nh = q >> 12;  int q2 = q & 4095;
        int kc = q2 >> 11; int q3 = q2 & 2047;
        int kh = q3 >> 10; int q4 = q3 & 1023;
        int n  = q4 >> 3;  int e  = q4 & 7;
        int k  = kc*16 + kh*8 + e;
        int ch = (s & 1)*32 + k;
        int pos = s >> 1;
        int ng = nh*128 + n;
        float v = w0[ng*576 + ch*9 + pos];
        __half hv = __float2half_rn(v);
        float lo = v - __half2float(hv);
        g_wHi2[i2] = hv;
        g_wLo2[i2] = __float2half_rn(lo);
    }
}

// ---------------- maps conv: k=64 stages, 3x32KB buffers (R14 proven) ----------------
#define T_SMEM 99328

__global__ void __launch_bounds__(256, 2) conv_maps(float* __restrict__ out)
{
    extern __shared__ char sm[];
    float* sal = (float*)(sm + 98304);
    float* sbe = (float*)(sm + 98816);
    const uint32_t sb = (uint32_t)__cvta_generic_to_shared(sm);

    const int tid = threadIdx.x;
    const int lane = tid & 31;
    const int w = tid >> 5;
    const int wm = w & 3, wn = w >> 2;
    const int g = lane >> 2, cc = lane & 3;
    const int hidx = blockIdx.y >> 1;
    const int nh   = blockIdx.y & 1;
    const int mtile = blockIdx.x;

    if (tid < 128) {
        sal[tid] = g_alpha[(hidx+1)*HCn + nh*128 + tid];
        sbe[tid] = g_beta [(hidx+1)*HCn + nh*128 + tid];
    }

    const int m = tid >> 1;
    const int kch = tid & 1;
    const int mg = mtile*128 + m;
    const int b = mg / HWn;
    const int rem = mg - b*HWn;
    const int y0 = rem / Wn;
    const int x0 = rem - y0*Wn;

    const __half* wsrcB = g_wB2h + (size_t)hidx*18*8192;

    auto issueS = [&](int s, int buf) {
        int ky = s/3, kx = s - ky*3;
        int gy = y0 + ky - 1, gx = x0 + kx - 1;
        bool valid = ((unsigned)gy < (unsigned)Hn) && ((unsigned)gx < (unsigned)Wn);
        unsigned sz = valid ? 16u : 0u;
        const __half* srcA = valid
            ? g_Xth + ((size_t)((b*Hn+gy)*Wn + gx))*64 + kch*32
            : g_Xth;
        uint32_t base = sb + buf*32768;
        uint32_t dA = base + (2*kch)*4096 + (m << 4);
        cpz(dA,               srcA,      sz);
        cpz(dA + 2048,        srcA + 8,  sz);
        cpz(dA + 4096,        srcA + 16, sz);
        cpz(dA + 4096 + 2048, srcA + 24, sz);
        const __half* srcB0 = wsrcB + (size_t)(2*s)  *8192 + nh*4096 + tid*16;
        const __half* srcB1 = wsrcB + (size_t)(2*s+1)*8192 + nh*4096 + tid*16;
        uint32_t dB = base + 16384 + tid*32;
        cpz(dB,           srcB0,     16);
        cpz(dB + 16,      srcB0 + 8, 16);
        cpz(dB + 8192,      srcB1,     16);
        cpz(dB + 8192 + 16, srcB1 + 8, 16);
    };

    const int mtx = lane >> 3;
    const uint32_t aoff = ((mtx>>1)*2048) + ((wm*32 + ((mtx&1)<<3) + (lane&7)) << 4);
    const uint32_t boff = ((mtx&1)*2048)  + ((wn*64 + ((mtx>>1)<<3) + (lane&7)) << 4);

    float acc[2][8][4];
    #pragma unroll
    for (int i=0;i<2;++i)
        #pragma unroll
        for (int j=0;j<8;++j)
            #pragma unroll
            for (int k=0;k<4;++k) acc[i][j][k]=0.f;

    issueS(0,0); CP_COMMIT();
    issueS(1,1); CP_COMMIT();

    for (int s = 0; s < NST_M; ++s) {
        const int buf = s % 3;
        if (s+1 < NST_M) { CP_WAIT(1); } else { CP_WAIT(0); }
        __syncthreads();

        const uint32_t aB = sb + buf*32768;
        const uint32_t bB = sb + buf*32768 + 16384;
        #pragma unroll
        for (int kc=0;kc<4;++kc) {
            uint32_t a0[4], a1[4], bf[4][4];
            ldm4(a0, aB + kc*4096 + aoff);
            ldm4(a1, aB + kc*4096 + aoff + 256);
            #pragma unroll
            for (int j=0;j<4;++j) ldm4(bf[j], bB + kc*4096 + boff + j*256);
            #pragma unroll
            for (int j=0;j<4;++j) {
                mma16(acc[0][2*j],   a0, bf[j][0], bf[j][1]);
                mma16(acc[0][2*j+1], a0, bf[j][2], bf[j][3]);
                mma16(acc[1][2*j],   a1, bf[j][0], bf[j][1]);
                mma16(acc[1][2*j+1], a1, bf[j][2], bf[j][3]);
            }
        }
        if (s+2 < NST_M) { issueS(s+2, (s+2)%3); CP_COMMIT(); }
    }

    const int bT = (mtile*128) / HWn;
    const int pT = mtile*128 - bT*HWn;
    float* obase = out + OFF_DEP + (size_t)hidx*MAP_N + (size_t)bT*HCn*HWn + pT;
    float* chunk = (float*)sm;

    for (int c = 0; c < 2; ++c) {
        __syncthreads();
        if (wn == c) {
            #pragma unroll
            for (int m2=0;m2<2;++m2)
                #pragma unroll
                for (int n2=0;n2<8;++n2)
                    #pragma unroll
                    for (int e=0;e<4;++e) {
                        int mrow = wm*32 + m2*16 + g + (e>>1)*8;
                        int ocl  = n2*8 + 2*cc + (e&1);
                        int oc   = c*64 + ocl;
                        float v = fmaxf(fmaf(acc[m2][n2][e], sal[oc], sbe[oc]), 0.f);
                        chunk[ocl*132 + mrow] = v;
                    }
        }
        __syncthreads();
        const float* sp = chunk + (tid>>2)*132 + (tid&3)*32;
        float* dst = obase + (size_t)(nh*128 + c*64 + (tid>>2))*HWn + (tid&3)*32;
        #pragma unroll
        for (int i=0;i<8;++i)
            ((float4*)dst)[i] = ((const float4*)sp)[i];
    }
}

// ---------------- hm conv: 3xFP16, fp32 acc (proven) ----------------
#define H_SMEM 102400

__global__ void __launch_bounds__(256, 2) conv_hm(const float* __restrict__ hm_w2)
{
    extern __shared__ char sm[];
    float* sal  = (float*)(sm + 98304);
    float* sbe  = (float*)(sm + 98816);
    float* sw2  = (float*)(sm + 99328);
    float* hmbuf= (float*)(sm + 100864);
    const uint32_t sb = (uint32_t)__cvta_generic_to_shared(sm);

    const int tid = threadIdx.x;
    const int lane = tid & 31;
    const int w = tid >> 5;
    const int wm = w & 3, wn = w >> 2;
    const int g = lane >> 2, cc = lane & 3;
    const int nh = blockIdx.y;
    const int mtile = blockIdx.x;

    if (tid < 128) {
        sal[tid] = g_alpha[nh*128 + tid];
        sbe[tid] = g_beta [nh*128 + tid];
        sw2[tid]       = hm_w2[nh*128 + tid];
        sw2[tid + 128] = hm_w2[256 + nh*128 + tid];
        sw2[tid + 256] = hm_w2[512 + nh*128 + tid];
        hmbuf[tid*3] = 0.f; hmbuf[tid*3+1] = 0.f; hmbuf[tid*3+2] = 0.f;
    }

    const int m = tid >> 1;
    const int kch = tid & 1;
    const int mg = mtile*128 + m;
    const int b = mg / HWn;
    const int rem = mg - b*HWn;
    const int y0 = rem / Wn;
    const int x0 = rem - y0*Wn;

    auto issueS = [&](int s, int buf) {
        int p = s >> 1;
        int ky = p/3, kx = p - ky*3;
        int gy = y0 + ky - 1, gx = x0 + kx - 1;
        bool valid = ((unsigned)gy < (unsigned)Hn) && ((unsigned)gx < (unsigned)Wn);
        unsigned sz = valid ? 16u : 0u;
        size_t po = valid ? ((size_t)((b*Hn+gy)*Wn + gx))*64 + (s&1)*32 + kch*16 : 0;
        const __half* sH = g_Xth  + po;
        const __half* sL = g_Xloh + po;
        uint32_t base = sb + buf*32768;
        uint32_t dA = base + (((kch*2)*128 + m) << 4);
        cpz(dA,               sH,     sz);
        cpz(dA + 2048,        sH + 8, sz);
        cpz(dA + 8192,        sL,     sz);
        cpz(dA + 8192 + 2048, sL + 8, sz);
        const __half* bh = g_wHi2 + (size_t)s*8192 + nh*4096 + tid*16;
        const __half* bl = g_wLo2 + (size_t)s*8192 + nh*4096 + tid*16;
        uint32_t dB = base + 16384 + tid*32;
        cpz(dB,             bh,     16);
        cpz(dB + 16,        bh + 8, 16);
        cpz(dB + 8192,      bl,     16);
        cpz(dB + 8192 + 16, bl + 8, 16);
    };

    const int mtx = lane >> 3;
    const uint32_t aoff = ((mtx>>1)*2048) + ((wm*32 + ((mtx&1)<<3) + (lane&7)) << 4);
    const uint32_t boff = ((mtx&1)*2048)  + ((wn*64 + ((mtx>>1)<<3) + (lane&7)) << 4);

    float acc[2][8][4];
    #pragma unroll
    for (int i=0;i<2;++i)
        #pragma unroll
        for (int j=0;j<8;++j)
            #pragma unroll
            for (int k=0;k<4;++k) acc[i][j][k]=0.f;

    issueS(0,0); CP_COMMIT();
    issueS(1,1); CP_COMMIT();

    for (int s = 0; s < NST_H; ++s) {
        const int buf = s % 3;
        if (s+1 < NST_H) { CP_WAIT(1); } else { CP_WAIT(0); }
        __syncthreads();

        const uint32_t base = sb + buf*32768;
        #pragma unroll
        for (int kc=0;kc<2;++kc) {
            uint32_t ah0[4], ah1[4], al0[4], al1[4], bf[4][4];
            ldm4(ah0, base + kc*4096 + aoff);
            ldm4(ah1, base + kc*4096 + aoff + 256);
            #pragma unroll
            for (int j=0;j<4;++j) ldm4(bf[j], base + 16384 + kc*4096 + boff + j*256);
            #pragma unroll
            for (int j=0;j<4;++j) {
                mma16(acc[0][2*j],   ah0, bf[j][0], bf[j][1]);
                mma16(acc[0][2*j+1], ah0, bf[j][2], bf[j][3]);
                mma16(acc[1][2*j],   ah1, bf[j][0], bf[j][1]);
                mma16(acc[1][2*j+1], ah1, bf[j][2], bf[j][3]);
            }
            ldm4(al0, base + 8192 + kc*4096 + aoff);
            ldm4(al1, base + 8192 + kc*4096 + aoff + 256);
            #pragma unroll
            for (int j=0;j<4;++j) {
                mma16(acc[0][2*j],   al0, bf[j][0], bf[j][1]);
                mma16(acc[0][2*j+1], al0, bf[j][2], bf[j][3]);
                mma16(acc[1][2*j],   al1, bf[j][0], bf[j][1]);
                mma16(acc[1][2*j+1], al1, bf[j][2], bf[j][3]);
            }
            #pragma unroll
            for (int j=0;j<4;++j) ldm4(bf[j], base + 24576 + kc*4096 + boff + j*256);
            #pragma unroll
            for (int j=0;j<4;++j) {
                mma16(acc[0][2*j],   ah0, bf[j][0], bf[j][1]);
                mma16(acc[0][2*j+1], ah0, bf[j][2], bf[j][3]);
                mma16(acc[1][2*j],   ah1, bf[j][0], bf[j][1]);
                mma16(acc[1][2*j+1], ah1, bf[j][2], bf[j][3]);
            }
        }
        if (s+2 < NST_H) { issueS(s+2, (s+2)%3); CP_COMMIT(); }
    }

    float hmacc[4][3];
    #pragma unroll
    for (int i=0;i<4;++i) { hmacc[i][0]=0.f; hmacc[i][1]=0.f; hmacc[i][2]=0.f; }

    #pragma unroll
    for (int m2=0;m2<2;++m2)
        #pragma unroll
        for (int n2=0;n2<8;++n2)
            #pragma unroll
            for (int e=0;e<4;++e) {
                int ocl = wn*64 + n2*8 + 2*cc + (e&1);
                float v = fmaxf(fmaf(acc[m2][n2][e], sal[ocl], sbe[ocl]), 0.f);
                int r = m2*2 + (e>>1);
                hmacc[r][0] = fmaf(sw2[ocl],       v, hmacc[r][0]);
                hmacc[r][1] = fmaf(sw2[128 + ocl], v, hmacc[r][1]);
                hmacc[r][2] = fmaf(sw2[256 + ocl], v, hmacc[r][2]);
            }
    #pragma unroll
    for (int o=1;o<4;o<<=1)
        #pragma unroll
        for (int i=0;i<4;++i)
            #pragma unroll
            for (int j=0;j<3;++j)
                hmacc[i][j] += __shfl_xor_sync(0xffffffffu, hmacc[i][j], o);

    __syncthreads();
    if (cc == 0) {
        #pragma unroll
        for (int m2=0;m2<2;++m2)
            #pragma unroll
            for (int t=0;t<2;++t) {
                int mrow = wm*32 + m2*16 + g + t*8;
                #pragma unroll
                for (int j=0;j<3;++j)
                    atomicAdd(&hmbuf[mrow*3 + j], hmacc[m2*2+t][j]);
            }
    }
    __syncthreads();

    if (tid < 128) {
        int midx = mtile*128 + tid;
        #pragma unroll
        for (int j=0;j<3;++j)
            g_hmpart[((size_t)nh*MTOT + midx)*3 + j] = hmbuf[tid*3 + j];
    }
}

// ---------------- heat finish ----------------
__global__ void heat_finish(const float* __restrict__ hm_b2, float* __restrict__ out)
{
    int idx = blockIdx.x * 256 + threadIdx.x;
    if (idx >= MTOT) return;
    int b = idx / HWn;
    int p = idx - b*HWn;
    #pragma unroll
    for (int j=0;j<3;++j) {
        float h = g_hmpart[(size_t)idx*3 + j] + g_hmpart[((size_t)MTOT + idx)*3 + j] + hm_b2[j];
        out[OFF_HEAT + (b*NCn + j)*HWn + p] = 1.f / (1.f + expf(-h));
    }
}

// ---------------- NMS on stored heat ----------------
__global__ void nms_kernel(const float* __restrict__ heat)
{
    int idx = blockIdx.x * blockDim.x + threadIdx.x;
    if (idx >= HEAT_N) return;
    int bc = idx / HWn;
    int p  = idx - bc * HWn;
    int y = p / Wn, x = p - y * Wn;
    const float* base = heat + bc * HWn;
    float c = base[p];
    float mx = c;
    #pragma unroll
    for (int dy = -1; dy <= 1; ++dy) {
        int yy = y + dy;
        if ((unsigned)yy >= (unsigned)Hn) continue;
        #pragma unroll
        for (int dx = -1; dx <= 1; ++dx) {
            int xx = x + dx;
            if ((unsigned)xx >= (unsigned)Wn) continue;
            float v = base[yy * Wn + xx];
            if (v > mx) mx = v;
        }
    }
    g_nms[idx] = (c == mx) ? c : 0.f;
}

// ---------------- per-batch global top-100 (radix select + bitonic) ----------------
__global__ void __launch_bounds__(1024) select_kernel(float* __restrict__ out)
{
    const int b = blockIdx.x;
    const int tid = threadIdx.x;
    const float* src = g_nms + (size_t)b * NCn * HWn;
    const int N = NCn * HWn;

    __shared__ unsigned hist[4096];
    __shared__ unsigned scan_s[32];
    __shared__ int sB1, sC1, sB2;
    __shared__ unsigned candK[512];
    __shared__ unsigned candI[512];
    __shared__ int ccnt;
    __shared__ unsigned long long skey[512];

    for (int i = tid; i < 4096; i += 1024) hist[i] = 0;
    __syncthreads();
    for (int i = tid; i < N; i += 1024) {
        unsigned u = __float_as_uint(src[i]);
        if (u) atomicAdd(&hist[u >> 19], 1);
    }
    __syncthreads();

    {
        int gb = 4*(1023 - tid);
        unsigned h0=hist[gb+3], h1=hist[gb+2], h2=hist[gb+1], h3=hist[gb];
        unsigned tsum = h0+h1+h2+h3;
        unsigned xv = tsum;
        #pragma unroll
        for (int o=1;o<32;o<<=1){ unsigned yv=__shfl_up_sync(0xffffffffu,xv,o); if ((tid&31)>=o) xv+=yv; }
        if ((tid&31)==31) scan_s[tid>>5] = xv;
        __syncthreads();
        if (tid < 32) {
            unsigned yv = scan_s[tid];
            #pragma unroll
            for (int o=1;o<32;o<<=1){ unsigned zv=__shfl_up_sync(0xffffffffu,yv,o); if (tid>=o) yv+=zv; }
            scan_s[tid] = yv;
        }
        __syncthreads();
        unsigned incl = xv + ((tid>=32) ? scan_s[(tid>>5)-1] : 0u);
        unsigned excl = incl - tsum;
        if (excl < (unsigned)Kn && incl >= (unsigned)Kn) {
            unsigned c = excl;
            if (c + h0 >= (unsigned)Kn)            { sB1 = gb+3; sC1 = (int)c; }
            else if (c + h0 + h1 >= (unsigned)Kn)  { sB1 = gb+2; sC1 = (int)(c+h0); }
            else if (c + h0 + h1 + h2 >= (unsigned)Kn) { sB1 = gb+1; sC1 = (int)(c+h0+h1); }
            else                                    { sB1 = gb;   sC1 = (int)(c+h0+h1+h2); }
        }
    }
    __syncthreads();
    const int B1 = sB1;
    const int need = Kn - sC1;

    for (int i = tid; i < 4096; i += 1024) hist[i] = 0;
    __syncthreads();
    for (int i = tid; i < N; i += 1024) {
        unsigned u = __float_as_uint(src[i]);
        if ((int)(u >> 19) == B1) atomicAdd(&hist[(u >> 7) & 0xFFF], 1);
    }
    __syncthreads();
    {
        int gb = 4*(1023 - tid);
        unsigned h0=hist[gb+3], h1=hist[gb+2], h2=hist[gb+1], h3=hist[gb];
        unsigned tsum = h0+h1+h2+h3;
        unsigned xv = tsum;
        #pragma unroll
        for (int o=1;o<32;o<<=1){ unsigned yv=__shfl_up_sync(0xffffffffu,xv,o); if ((tid&31)>=o) xv+=yv; }
        if ((tid&31)==31) scan_s[tid>>5] = xv;
        __syncthreads();
        if (tid < 32) {
            unsigned yv = scan_s[tid];
            #pragma unroll
            for (int o=1;o<32;o<<=1){ unsigned zv=__shfl_up_sync(0xffffffffu,yv,o); if (tid>=o) yv+=zv; }
            scan_s[tid] = yv;
        }
        __syncthreads();
        unsigned incl = xv + ((tid>=32) ? scan_s[(tid>>5)-1] : 0u);
        unsigned excl = incl - tsum;
        if (excl < (unsigned)need && incl >= (unsigned)need) {
            unsigned c = excl;
            if (c + h0 >= (unsigned)need)            sB2 = gb+3;
            else if (c + h0 + h1 >= (unsigned)need)  sB2 = gb+2;
            else if (c + h0 + h1 + h2 >= (unsigned)need) sB2 = gb+1;
            else                                      sB2 = gb;
        }
        if (tid == 0) ccnt = 0;
    }
    __syncthreads();

    const unsigned thr = ((unsigned)B1 << 12) | (unsigned)sB2;
    for (int i = tid; i < N; i += 1024) {
        unsigned u = __float_as_uint(src[i]);
        if ((u >> 7) >= thr) {
            int pos = atomicAdd(&ccnt, 1);
            if (pos < 512) { candK[pos] = u; candI[pos] = (unsigned)i; }
        }
    }
    __syncthreads();

    int n = ccnt; if (n > 512) n = 512;
    for (int i = tid; i < 512; i += 1024)
        skey[i] = (i < n)
            ? ((unsigned long long)candK[i] << 32) | (unsigned)(0xFFFFFFFFu - candI[i])
            : 0ull;
    __syncthreads();
    for (int k = 2; k <= 512; k <<= 1) {
        for (int j = k >> 1; j > 0; j >>= 1) {
            for (int i = tid; i < 512; i += 1024) {
                int ix = i ^ j;
                if (ix > i) {
                    unsigned long long a = skey[i], c = skey[ix];
                    bool desc = ((i & k) == 0);
                    bool sw = desc ? (a < c) : (a > c);
                    if (sw) { skey[i] = c; skey[ix] = a; }
                }
            }
            __syncthreads();
        }
    }

    if (tid < Kn) {
        unsigned long long e = skey[tid];
        unsigned key = (unsigned)(e >> 32);
        unsigned fi  = 0xFFFFFFFFu - (unsigned)(e & 0xFFFFFFFFu);
        out[OFF_SCORES + b*Kn + tid] = __uint_as_float(key);
        g_sel[b*Kn + tid] = (int)(fi % HWn);
    }
}

// ---------------- gather ----------------
__global__ void __launch_bounds__(384) gather_kernel(
    const float* __restrict__ up8, const float* __restrict__ up16, float* __restrict__ out)
{
    int bk = blockIdx.x;
    int b  = bk / Kn;
    int c  = threadIdx.x;
    int ind = g_sel[bk];
    if (ind < 0) ind = 0;
    if (ind > HWn - 1) ind = HWn - 1;
    float val;
    if (c < 128)
        val = up8 [((long long)b*128 + c)       * HWn + (ind >> 1)];
    else
        val = up16[((long long)b*256 + (c-128)) * HWn + (ind >> 2)];
    out[OFF_POIS + bk*384 + c] = val;
}

// ---------------- reg3d ----------------
__global__ void reg3d_kernel(const float* __restrict__ r3b, float* __restrict__ out)
{
    int idx = blockIdx.x * blockDim.x + threadIdx.x;
    if (idx >= REG3D_N) return;
    int o = (idx / (64*320)) & 7;
    out[OFF_REG3D + idx] = g_rs[o] + r3b[o];
}

// ---------------- launch: forked streams so conv_hm chain overlaps conv_maps ----------------
extern "C" void kernel_launch(void* const* d_in, const int* in_sizes, int n_in,
                              void* d_out, int out_size)
{
    const float* up16 = (const float*)d_in[0];
    const float* up8  = (const float*)d_in[1];
    const float* up4  = (const float*)d_in[2];

    const float* hm_w1  = (const float*)d_in[3];
    const float* dep_w1 = (const float*)d_in[9];
    const float* dim_w1 = (const float*)d_in[15];
    const float* rot_w1 = (const float*)d_in[21];
    const float* hm_w2  = (const float*)d_in[27];
    const float* hm_b2  = (const float*)d_in[28];
    const float* r3w    = (const float*)d_in[29];
    const float* r3b    = (const float*)d_in[30];

    float* out = (float*)d_out;

    cudaFuncSetAttribute(conv_maps, cudaFuncAttributeMaxDynamicSharedMemorySize, T_SMEM);
    cudaFuncSetAttribute(conv_hm,   cudaFuncAttributeMaxDynamicSharedMemorySize, H_SMEM);

    cudaStream_t s2;
    cudaStreamCreateWithFlags(&s2, cudaStreamNonBlocking);
    cudaEvent_t evF, evJ;
    cudaEventCreateWithFlags(&evF, cudaEventDisableTiming);
    cudaEventCreateWithFlags(&evJ, cudaEventDisableTiming);

    prep_kernel<<<1, 1024>>>(
        (const float*)d_in[4],  (const float*)d_in[5],  (const float*)d_in[6],  (const float*)d_in[7],  (const float*)d_in[8],
        (const float*)d_in[10], (const float*)d_in[11], (const float*)d_in[12], (const float*)d_in[13], (const float*)d_in[14],
        (const float*)d_in[16], (const float*)d_in[17], (const float*)d_in[18], (const float*)d_in[19], (const float*)d_in[20],
        (const float*)d_in[22], (const float*)d_in[23], (const float*)d_in[24], (const float*)d_in[25], (const float*)d_in[26],
        r3w);
    xt_kernel<<<MTOT/32, 256>>>(up4);
    packW<<<(WMAPS_N + WHM_N + 255)/256, 256>>>(hm_w1, dep_w1, dim_w1, rot_w1);

    // fork: hm chain + tail on s2, maps on origin stream
    cudaEventRecord(evF, 0);
    cudaStreamWaitEvent(s2, evF, 0);

    conv_hm<<<dim3(960, 2), 256, H_SMEM, s2>>>(hm_w2);
    heat_finish<<<(MTOT + 255)/256, 256, 0, s2>>>(hm_b2, out);
    nms_kernel<<<(HEAT_N + 255)/256, 256, 0, s2>>>(out + OFF_HEAT);
    select_kernel<<<Bn, 1024, 0, s2>>>(out);
    gather_kernel<<<Bn*Kn, 384, 0, s2>>>(up8, up16, out);
    reg3d_kernel<<<(REG3D_N + 511)/512, 512, 0, s2>>>(r3b, out);
    cudaEventRecord(evJ, s2);

    conv_maps<<<dim3(960, 6), 256, T_SMEM>>>(out);

    // join
    cudaStreamWaitEvent(0, evJ, 0);
}